// round 3
// baseline (speedup 1.0000x reference)
#include <cuda_runtime.h>
#include <math.h>
#include <stdint.h>

#define NB   1024
#define NS   500
#define NP   (NS/2)        // sample pairs per ray
#define RR   128
#define LATC 12
#define FEATC 64
#define HIDC 128
#define CINC 21            // 9 raw inputs + 12 folded latent channels
#define GC   13            // grid channels: 1 sdf + 12 latent

// ---------------- scratch (static device arrays; no runtime alloc) ----------
__device__ float  g_sdf[NB * NS];
__device__ float4 g_rgbp[NB * NS];    // xyz = rgb, w unused (16B aligned)
__device__ float  g_cw[CINC * HIDC];  // combined first-layer weights
__device__ float  g_cb[HIDC];         // combined first-layer bias
__device__ float  g_w2t[3 * HIDC];    // W2 transposed [c][j]
__device__ float  g_b2c[3];

// ---------------- prep: fold feature layer into W1 (split-K parallel) -------
// grid = 13 blocks x 512 threads. thread = (j = tid&127, q = tid>>7).
// blocks 0..11: W_eff[l][j] = Wf[l,:] @ W1[9:,j], 16-term partial per q.
// block 12: bias fold + row copies + W2 transpose.
__global__ void __launch_bounds__(512)
prep_kernel(const float* __restrict__ Wf, const float* __restrict__ bf,
            const float* __restrict__ W1, const float* __restrict__ b1,
            const float* __restrict__ W2, const float* __restrict__ b2) {
    __shared__ float red[4][HIDC];
    int tid = threadIdx.x;
    int j = tid & (HIDC - 1);
    int q = tid >> 7;              // 0..3
    int l = blockIdx.x;

    if (l < LATC) {
        float a0 = 0.f, a1 = 0.f;
        int c0 = q * 16;
#pragma unroll
        for (int c = 0; c < 16; c += 2) {
            a0 = fmaf(Wf[l * FEATC + c0 + c + 0], W1[(9 + c0 + c + 0) * HIDC + j], a0);
            a1 = fmaf(Wf[l * FEATC + c0 + c + 1], W1[(9 + c0 + c + 1) * HIDC + j], a1);
        }
        red[q][j] = a0 + a1;
        __syncthreads();
        if (q == 0)
            g_cw[(9 + l) * HIDC + j] =
                (red[0][j] + red[1][j]) + (red[2][j] + red[3][j]);
    } else {
        // bias partial
        float a0 = 0.f, a1 = 0.f;
        int c0 = q * 16;
#pragma unroll
        for (int c = 0; c < 16; c += 2) {
            a0 = fmaf(bf[c0 + c + 0], W1[(9 + c0 + c + 0) * HIDC + j], a0);
            a1 = fmaf(bf[c0 + c + 1], W1[(9 + c0 + c + 1) * HIDC + j], a1);
        }
        red[q][j] = a0 + a1;
        // rows 0..8 of g_cw == first 9*128 floats of W1: straight copy
        for (int i = tid; i < 9 * HIDC; i += 512) g_cw[i] = W1[i];
        // W2 transpose
        for (int i = tid; i < 3 * HIDC; i += 512) {
            int c = i / HIDC, jj = i - c * HIDC;
            g_w2t[i] = W2[jj * 3 + c];
        }
        if (tid < 3) g_b2c[tid] = b2[tid];
        __syncthreads();
        if (q == 0)
            g_cb[j] = b1[j] + ((red[0][j] + red[1][j]) + (red[2][j] + red[3][j]));
    }
}

// ---------------- per-point-pair: trilerp + grad + MLP ----------------------
__device__ __forceinline__ void trilerp_grad(
    const float* __restrict__ grid, float px, float py, float pz,
    float* vv, float& gxa, float& gya, float& gza) {
    float ux = fminf(fmaxf((px + 1.0f) * 0.5f * 127.0f, 0.0f), 127.0f);
    float uy = fminf(fmaxf((py + 1.0f) * 0.5f * 127.0f, 0.0f), 127.0f);
    float uz = fminf(fmaxf((pz + 1.0f) * 0.5f * 127.0f, 0.0f), 127.0f);
    int ix = min((int)ux, RR - 2);
    int iy = min((int)uy, RR - 2);
    int iz = min((int)uz, RR - 2);
    float fx = ux - (float)ix, fy = uy - (float)iy, fz = uz - (float)iz;
    float wx[2] = {1.0f - fx, fx};
    float wy[2] = {1.0f - fy, fy};
    float wz[2] = {1.0f - fz, fz};
    const float* gp = grid + ((size_t)((ix * RR + iy) * RR + iz)) * GC;
#pragma unroll
    for (int c = 0; c < GC; c++) vv[c] = 0.0f;
    gxa = gya = gza = 0.0f;
#pragma unroll
    for (int cx = 0; cx < 2; cx++) {
#pragma unroll
        for (int cy = 0; cy < 2; cy++) {
#pragma unroll
            for (int cz = 0; cz < 2; cz++) {
                const float* cp = gp + cx * (RR * RR * GC) + cy * (RR * GC) + cz * GC;
                float wyz = wy[cy] * wz[cz];
                float wxz = wx[cx] * wz[cz];
                float wxy = wx[cx] * wy[cy];
                float w   = wx[cx] * wyz;
                float c0  = cp[0];
                vv[0] = fmaf(w, c0, vv[0]);
                gxa = fmaf(cx ? wyz : -wyz, c0, gxa);
                gya = fmaf(cy ? wxz : -wxz, c0, gya);
                gza = fmaf(cz ? wxy : -wxy, c0, gza);
#pragma unroll
                for (int c = 1; c < GC; c++) vv[c] = fmaf(w, cp[c], vv[c]);
            }
        }
    }
}

__global__ void __launch_bounds__(256)
point_kernel(const float* __restrict__ ro, const float* __restrict__ rd,
             const float* __restrict__ vdir, const float* __restrict__ grid) {
    __shared__ float sW[CINC * HIDC];
    __shared__ float sB[HIDC];
    __shared__ float sW2[3 * HIDC];
    __shared__ float sB2[4];

    // thread handles samples s0 = 2*rem, s0+1 of ray = idx / NP
    int idx = blockIdx.x * blockDim.x + threadIdx.x;   // NB*NP == 256000 == 1000*256
    int ray = idx / NP;
    int s0  = (idx - ray * NP) * 2;
    int base = ray * NS + s0;

    float ox = ro[ray * 3 + 0], oy = ro[ray * 3 + 1], oz = ro[ray * 3 + 2];
    float dx = rd[ray * 3 + 0], dy = rd[ray * 3 + 1], dz = rd[ray * 3 + 2];

    // non-fused math to bit-match XLA's mul+add for the mask decision
    float linA = __fmul_rn((float)s0, 1.0f / 499.0f);
    float zA   = __fadd_rn(0.5f, __fmul_rn(3.0f, linA));
    float pxA = __fadd_rn(ox, __fmul_rn(dx, zA));
    float pyA = __fadd_rn(oy, __fmul_rn(dy, zA));
    float pzA = __fadd_rn(oz, __fmul_rn(dz, zA));
    float linB = __fmul_rn((float)(s0 + 1), 1.0f / 499.0f);
    float zB   = __fadd_rn(0.5f, __fmul_rn(3.0f, linB));
    float pxB = __fadd_rn(ox, __fmul_rn(dx, zB));
    float pyB = __fadd_rn(oy, __fmul_rn(dy, zB));
    float pzB = __fadd_rn(oz, __fmul_rn(dz, zB));

    bool outA = (pxA < -1.0f) | (pxA > 1.0f) | (pyA < -1.0f) | (pyA > 1.0f) |
                (pzA < -1.0f) | (pzA > 1.0f);
    bool outB = (pxB < -1.0f) | (pxB > 1.0f) | (pyB < -1.0f) | (pyB > 1.0f) |
                (pzB < -1.0f) | (pzB > 1.0f);
    if (outA) g_sdf[base + 0] = 100.0f;   // rgb scratch untouched: weight is exact 0
    if (outB) g_sdf[base + 1] = 100.0f;

    bool live = !(outA && outB);
    int act = __syncthreads_count(live);
    if (act == 0) return;                 // whole block outside: skip weights

    for (int i = threadIdx.x; i < CINC * HIDC; i += blockDim.x) sW[i] = g_cw[i];
    for (int i = threadIdx.x; i < HIDC; i += blockDim.x) sB[i] = g_cb[i];
    for (int i = threadIdx.x; i < 3 * HIDC; i += blockDim.x) sW2[i] = g_w2t[i];
    if (threadIdx.x < 3) sB2[threadIdx.x] = g_b2c[threadIdx.x];
    __syncthreads();
    if (!live) return;

    float vx = vdir[ray * 3 + 0], vy = vdir[ray * 3 + 1], vz = vdir[ray * 3 + 2];

    float vvA[GC], vvB[GC];
    float gxA, gyA, gzA, gxB, gyB, gzB;
    trilerp_grad(grid, pxA, pyA, pzA, vvA, gxA, gyA, gzA);
    trilerp_grad(grid, pxB, pyB, pzB, vvB, gxB, gyB, gzB);

    float hA[CINC], hB[CINC];
    hA[0] = pxA; hA[1] = pyA; hA[2] = pzA;
    hA[3] = gxA * 63.5f; hA[4] = gyA * 63.5f; hA[5] = gzA * 63.5f;
    hA[6] = vx; hA[7] = vy; hA[8] = vz;
    hB[0] = pxB; hB[1] = pyB; hB[2] = pzB;
    hB[3] = gxB * 63.5f; hB[4] = gyB * 63.5f; hB[5] = gzB * 63.5f;
    hB[6] = vx; hB[7] = vy; hB[8] = vz;
#pragma unroll
    for (int l = 0; l < LATC; l++) { hA[9 + l] = vvA[1 + l]; hB[9 + l] = vvB[1 + l]; }

    // ---- MLP for both samples; each weight float4 feeds 8 FMAs ----
    const float4* sW4  = (const float4*)sW;
    const float4* sB4  = (const float4*)sB;
    const float4* sW24 = (const float4*)sW2;
    float rA0 = 0.f, rA1 = 0.f, rA2 = 0.f;
    float rB0 = 0.f, rB1 = 0.f, rB2 = 0.f;
    for (int jq = 0; jq < HIDC / 4; jq++) {
        float4 bq = sB4[jq];
        float4 a = bq, b = bq;
#pragma unroll
        for (int k = 0; k < CINC; k++) {
            float4 wv = sW4[k * (HIDC / 4) + jq];
            a.x = fmaf(hA[k], wv.x, a.x); b.x = fmaf(hB[k], wv.x, b.x);
            a.y = fmaf(hA[k], wv.y, a.y); b.y = fmaf(hB[k], wv.y, b.y);
            a.z = fmaf(hA[k], wv.z, a.z); b.z = fmaf(hB[k], wv.z, b.z);
            a.w = fmaf(hA[k], wv.w, a.w); b.w = fmaf(hB[k], wv.w, b.w);
        }
        a.x = fmaxf(a.x, 0.f); a.y = fmaxf(a.y, 0.f);
        a.z = fmaxf(a.z, 0.f); a.w = fmaxf(a.w, 0.f);
        b.x = fmaxf(b.x, 0.f); b.y = fmaxf(b.y, 0.f);
        b.z = fmaxf(b.z, 0.f); b.w = fmaxf(b.w, 0.f);
        float4 w0 = sW24[0 * (HIDC / 4) + jq];
        float4 w1 = sW24[1 * (HIDC / 4) + jq];
        float4 w2 = sW24[2 * (HIDC / 4) + jq];
        rA0 = fmaf(a.x, w0.x, fmaf(a.y, w0.y, fmaf(a.z, w0.z, fmaf(a.w, w0.w, rA0))));
        rA1 = fmaf(a.x, w1.x, fmaf(a.y, w1.y, fmaf(a.z, w1.z, fmaf(a.w, w1.w, rA1))));
        rA2 = fmaf(a.x, w2.x, fmaf(a.y, w2.y, fmaf(a.z, w2.z, fmaf(a.w, w2.w, rA2))));
        rB0 = fmaf(b.x, w0.x, fmaf(b.y, w0.y, fmaf(b.z, w0.z, fmaf(b.w, w0.w, rB0))));
        rB1 = fmaf(b.x, w1.x, fmaf(b.y, w1.y, fmaf(b.z, w1.z, fmaf(b.w, w1.w, rB1))));
        rB2 = fmaf(b.x, w2.x, fmaf(b.y, w2.y, fmaf(b.z, w2.z, fmaf(b.w, w2.w, rB2))));
    }
    if (!outA) {
        g_sdf[base + 0] = vvA[0];
        g_rgbp[base + 0] = make_float4(
            1.0f / (1.0f + expf(-(rA0 + sB2[0]))),
            1.0f / (1.0f + expf(-(rA1 + sB2[1]))),
            1.0f / (1.0f + expf(-(rA2 + sB2[2]))), 0.0f);
    }
    if (!outB) {
        g_sdf[base + 1] = vvB[0];
        g_rgbp[base + 1] = make_float4(
            1.0f / (1.0f + expf(-(rB0 + sB2[0]))),
            1.0f / (1.0f + expf(-(rB1 + sB2[1]))),
            1.0f / (1.0f + expf(-(rB2 + sB2[2]))), 0.0f);
    }
}

// ---------------- per-ray: transmittance scan + accumulation ----------------
__global__ void __launch_bounds__(256)
integrate_kernel(const float* __restrict__ rd, const float* __restrict__ beta_p,
                 float* __restrict__ out) {
    int gwarp = (blockIdx.x * blockDim.x + threadIdx.x) >> 5;
    int lane  = threadIdx.x & 31;
    if (gwarp >= NB) return;
    const unsigned FULL = 0xffffffffu;

    float beff = fabsf(beta_p[0]) + 1e-4f;
    float rb   = 1.0f / beff;
    float dx = rd[gwarp * 3 + 0], dy = rd[gwarp * 3 + 1], dz = rd[gwarp * 3 + 2];
    float dn = sqrtf(dx * dx + dy * dy + dz * dz);

    float carry = 0.0f, aR = 0.0f, aG = 0.0f, aB = 0.0f, aD = 0.0f;

    for (int chunk = 0; chunk < (NS + 31) / 32; chunk++) {
        int s = chunk * 32 + lane;
        bool in = s < NS;
        float sdf = in ? g_sdf[gwarp * NS + s] : 100.0f;

        float lin = __fmul_rn((float)s, 1.0f / 499.0f);
        float z   = __fadd_rn(0.5f, __fmul_rn(3.0f, lin));
        int sd = (s >= NS - 1) ? NS - 2 : s;
        float l0 = __fmul_rn((float)sd, 1.0f / 499.0f);
        float l1 = __fmul_rn((float)(sd + 1), 1.0f / 499.0f);
        float z0 = __fadd_rn(0.5f, __fmul_rn(3.0f, l0));
        float z1 = __fadd_rn(0.5f, __fmul_rn(3.0f, l1));
        float dist = z1 - z0;

        float asdf = fabsf(sdf);
        float sgn  = (sdf > 0.0f) ? 1.0f : ((sdf < 0.0f) ? -1.0f : 0.0f);
        float density = rb * (0.5f + 0.5f * sgn * expm1f(-asdf / beff));
        float fe = in ? dist * density : 0.0f;

        // inclusive warp scan of fe
        float sc = fe;
#pragma unroll
        for (int o = 1; o < 32; o <<= 1) {
            float t = __shfl_up_sync(FULL, sc, o);
            if (lane >= o) sc += t;
        }
        float T     = expf(-(carry + (sc - fe)));   // exclusive prefix
        float alpha = 1.0f - expf(-fe);
        float w     = in ? alpha * T : 0.0f;

        if (in && w != 0.0f) {
            float4 c = g_rgbp[gwarp * NS + s];
            aR = fmaf(w, c.x, aR);
            aG = fmaf(w, c.y, aG);
            aB = fmaf(w, c.z, aB);
        }
        if (in) aD = fmaf(w, z * dn, aD);
        carry += __shfl_sync(FULL, sc, 31);
    }

#pragma unroll
    for (int o = 16; o > 0; o >>= 1) {
        aR += __shfl_down_sync(FULL, aR, o);
        aG += __shfl_down_sync(FULL, aG, o);
        aB += __shfl_down_sync(FULL, aB, o);
        aD += __shfl_down_sync(FULL, aD, o);
    }
    if (lane == 0) {
        out[gwarp * 3 + 0] = aR;
        out[gwarp * 3 + 1] = aG;
        out[gwarp * 3 + 2] = aB;
        out[3 * NB + gwarp] = aD;
    }
}

// ---------------- launch -----------------------------------------------------
extern "C" void kernel_launch(void* const* d_in, const int* in_sizes, int n_in,
                              void* d_out, int out_size) {
    const float* ro   = (const float*)d_in[0];
    const float* rd   = (const float*)d_in[1];
    const float* vd   = (const float*)d_in[2];
    const float* grid = (const float*)d_in[3];
    const float* Wf   = (const float*)d_in[4];
    const float* bf   = (const float*)d_in[5];
    const float* W1   = (const float*)d_in[6];
    const float* b1   = (const float*)d_in[7];
    const float* W2   = (const float*)d_in[8];
    const float* b2   = (const float*)d_in[9];
    const float* beta = (const float*)d_in[10];
    float* out = (float*)d_out;

    prep_kernel<<<LATC + 1, 512>>>(Wf, bf, W1, b1, W2, b2);
    point_kernel<<<(NB * NP) / 256, 256>>>(ro, rd, vd, grid);
    integrate_kernel<<<(NB * 32 + 255) / 256, 256>>>(rd, beta, out);
}